// round 4
// baseline (speedup 1.0000x reference)
#include <cuda_runtime.h>
#include <cuda_bf16.h>
#include <cuda_fp8.h>
#include <cstdint>

#define HEADS 12
#define HEAD_S 64
#define BATCH 32
#define SEQ 512
#define DIM 768
#define NPROJ (HEADS * HEAD_S * 2)   // 1536
#define MROWS (BATCH * SEQ)          // 16384
#define NEGC 1000000000000.0f
#define NEG8 (NEGC * 0.125f)
#define WSCALE 32.0f
#define QKSCALE 8.0f

// -------- scratch (device globals; no allocation allowed) --------
__device__ unsigned char g_x8[(size_t)MROWS * DIM];            // e4m3 x
__device__ unsigned char g_W8[(size_t)NPROJ * DIM];            // e4m3 W^T * 32, [n][k]
__device__ unsigned char g_Q[(size_t)BATCH * HEADS * SEQ * HEAD_S];  // e4m3 *8
__device__ unsigned char g_K[(size_t)BATCH * HEADS * SEQ * HEAD_S];  // e4m3 *8
__device__ float g_sin[SEQ * 32];
__device__ float g_cos[SEQ * 32];

// -------- helpers --------
__device__ __forceinline__ uint32_t saddr(const void* p) {
    return (uint32_t)__cvta_generic_to_shared(p);
}
// pack two floats -> e4m3x2 (lo, hi)
__device__ __forceinline__ unsigned short pk8(float lo, float hi) {
    unsigned short r;
    asm("cvt.rn.satfinite.e4m3x2.f32 %0, %1, %2;" : "=h"(r) : "f"(hi), "f"(lo));
    return r;
}
__device__ __forceinline__ void cpasync16s(uint32_t s, const void* gmem) {
    asm volatile("cp.async.cg.shared.global [%0], [%1], 16;" :: "r"(s), "l"(gmem));
}
#define CP_COMMIT asm volatile("cp.async.commit_group;")
#define CP_WAIT(n) asm volatile("cp.async.wait_group %0;" :: "n"(n))

__device__ __forceinline__ void ldmx4(unsigned* r, uint32_t addr) {
    asm volatile("ldmatrix.sync.aligned.m8n8.x4.shared.b16 {%0,%1,%2,%3},[%4];"
                 : "=r"(r[0]), "=r"(r[1]), "=r"(r[2]), "=r"(r[3]) : "r"(addr));
}
// fp8 e4m3 MMA: D(16x8,f32) += A(16x32) * B(8x32)^T
__device__ __forceinline__ void mma8(float* c, const unsigned* a, const unsigned* b) {
    asm volatile(
        "mma.sync.aligned.m16n8k32.row.col.f32.e4m3.e4m3.f32 "
        "{%0,%1,%2,%3},{%4,%5,%6,%7},{%8,%9},{%0,%1,%2,%3};"
        : "+f"(c[0]), "+f"(c[1]), "+f"(c[2]), "+f"(c[3])
        : "r"(a[0]), "r"(a[1]), "r"(a[2]), "r"(a[3]), "r"(b[0]), "r"(b[1]));
}

// =============================================================
// Fused prep: x->e4m3 (blocks 0..6143), W^T*32->e4m3 (6144..7295),
//             rope table (7296..7359)
// =============================================================
#define PREP_XBLK 6144
#define PREP_WBLK 1152
#define PREP_RBLK 64
__global__ __launch_bounds__(256) void prep(const float* __restrict__ x,
                                            const float* __restrict__ W) {
    __shared__ float t[32][33];
    int bid = blockIdx.x, tid = threadIdx.x;
    if (bid < PREP_XBLK) {
        size_t i = ((size_t)bid * 256 + tid) * 8;
        const float4* p = (const float4*)(x + i);
        float4 u = p[0], v = p[1];
        ushort4 w;
        w.x = pk8(u.x, u.y); w.y = pk8(u.z, u.w);
        w.z = pk8(v.x, v.y); w.w = pk8(v.z, v.w);
        *(ushort4*)&g_x8[i] = w;
    } else if (bid < PREP_XBLK + PREP_WBLK) {
        int tile = bid - PREP_XBLK;
        int nt = (tile % 48) * 32, kt = (tile / 48) * 32;
        int tx = tid & 31, ty = tid >> 5;
        for (int i2 = ty; i2 < 32; i2 += 8)
            t[i2][tx] = W[(size_t)(kt + i2) * NPROJ + nt + tx];
        __syncthreads();
        for (int i2 = ty; i2 < 32; i2 += 8)
            g_W8[(size_t)(nt + i2) * DIM + kt + tx] =
                __nv_cvt_float_to_fp8(t[tx][i2] * WSCALE, __NV_SATFINITE, __NV_E4M3);
    } else {
        int idx = (bid - PREP_XBLK - PREP_WBLK) * 256 + tid;  // < 16384
        int l = idx >> 5, i2 = idx & 31;
        float freq = powf(10000.0f, -(2.0f * (float)i2) / 64.0f);
        float ang = (float)l * freq;
        g_sin[idx] = sinf(ang);
        g_cos[idx] = cosf(ang);
    }
}

// =============================================================
// Stage 1 (fp8 mma.sync): proj = x @ W + b, RoPE, write Q/K e4m3
// CTA tile 128(m) x 128(n=one head), BK=128 bytes, 6 k-blocks,
// 2-stage cp.async. smem rows padded to 144B (conflict-free ldmatrix).
// =============================================================
#define SROW1 144
#define S1_TILE (128 * SROW1)                 // 18432 B
#define S1_STAGE (2 * S1_TILE)                // A + B
#define S1_SMEM (2 * S1_STAGE)                // 73728 B

__global__ __launch_bounds__(256) void stage1(const float* __restrict__ bias) {
    extern __shared__ char sm[];
    __shared__ float sBias[128];
    uint32_t tb = saddr(sm);

    int tid = threadIdx.x, warp = tid >> 5, lane = tid & 31;
    int head = blockIdx.x, mblk = blockIdx.y;
    int wm = (warp >> 1) * 32;
    int wn = (warp & 1) * 64;

    if (tid < 128) sBias[tid] = bias[head * 128 + tid];

    const unsigned char* xb = g_x8 + (size_t)mblk * 128 * DIM;
    const unsigned char* wb = g_W8 + (size_t)head * 128 * DIM;
    int lrow = tid >> 3;
    int lc16 = (tid & 7) * 16;

    auto issue = [&](int buf, int t) {
        uint32_t ab = tb + buf * S1_STAGE;
        uint32_t bb = ab + S1_TILE;
        const unsigned char* xp = xb + t * 128 + lc16;
        const unsigned char* wp = wb + t * 128 + lc16;
#pragma unroll
        for (int it = 0; it < 4; it++) {
            int row = it * 32 + lrow;
            uint32_t o = row * SROW1 + lc16;
            cpasync16s(ab + o, xp + (size_t)row * DIM);
            cpasync16s(bb + o, wp + (size_t)row * DIM);
        }
        CP_COMMIT;
    };

    float acc[2][8][4];
#pragma unroll
    for (int a = 0; a < 2; a++)
#pragma unroll
        for (int b = 0; b < 8; b++)
#pragma unroll
            for (int c = 0; c < 4; c++) acc[a][b][c] = 0.0f;

    issue(0, 0);
    issue(1, 1);

    const int NK = 6;
    for (int i = 0; i < NK; i++) {
        if (i == NK - 1) { CP_WAIT(0); } else { CP_WAIT(1); }
        __syncthreads();
        uint32_t ab = tb + (i & 1) * S1_STAGE;
        uint32_t bb = ab + S1_TILE;
#pragma unroll
        for (int ks = 0; ks < 4; ks++) {
            int kb = ks * 32;                          // byte offset
            unsigned a[2][4], bf[4][4];
#pragma unroll
            for (int mt = 0; mt < 2; mt++) {
                int r = wm + mt * 16 + (lane & 7) + ((lane >> 3) & 1) * 8;
                int c = kb + (lane >> 4) * 16;
                ldmx4(a[mt], ab + r * SROW1 + c);
            }
#pragma unroll
            for (int np = 0; np < 4; np++) {
                int g = lane >> 3;
                int r = wn + np * 16 + (lane & 7) + (g >> 1) * 8;
                int c = kb + (g & 1) * 16;
                ldmx4(bf[np], bb + r * SROW1 + c);
            }
#pragma unroll
            for (int mt = 0; mt < 2; mt++)
#pragma unroll
                for (int np = 0; np < 4; np++) {
                    mma8(acc[mt][2 * np],     a[mt], &bf[np][0]);  // n8 tile 0: k0-15,k16-31
                    mma8(acc[mt][2 * np + 1], a[mt], &bf[np][2]);  // n8 tile 1
                }
        }
        __syncthreads();
        if (i + 2 < NK) issue(i & 1, i + 2);
    }

    // epilogue: v = acc/32 + bias, RoPE, write Q/K e4m3 (*8)
    int gmb = mblk * 128;
    const float inv = 1.0f / WSCALE;
#pragma unroll
    for (int mt = 0; mt < 2; mt++) {
#pragma unroll
        for (int nt = 0; nt < 8; nt++) {
            int ncol = wn + nt * 8 + 2 * (lane & 3);   // even, [0,128)
            int rch = ncol & 63;
            int i = rch >> 1;
            bool isQ = ncol < 64;
            int ngl = head * 128 + ncol;
            float b0 = sBias[ngl - head * 128], b1 = sBias[ngl - head * 128 + 1];
#pragma unroll
            for (int rr = 0; rr < 2; rr++) {
                int row = wm + mt * 16 + (lane >> 2) + rr * 8;
                int gm = gmb + row;
                int bb2 = gm >> 9;
                int l = gm & 511;
                float v0 = acc[mt][nt][rr * 2 + 0] * inv + b0;
                float v1 = acc[mt][nt][rr * 2 + 1] * inv + b1;
                float sn = g_sin[l * 32 + i], cs = g_cos[l * 32 + i];
                float o0 = (v0 * cs - v1 * sn) * QKSCALE;
                float o1 = (v1 * cs + v0 * sn) * QKSCALE;
                size_t off = (((size_t)(bb2 * HEADS + head) * SEQ + l) * HEAD_S + rch);
                unsigned char* dst = (isQ ? g_Q : g_K) + off;
                *(unsigned short*)dst = pk8(o0, o1);
            }
        }
    }
}

// =============================================================
// Stage 2 (fp8 mma.sync): per (b,h): S = Q @ K^T, mask+tril+scale
// block tile 128x128, grid (4 ntiles, 4 mtiles, 384 bh)
// =============================================================
#define SROW2 80
__global__ __launch_bounds__(256) void stage2(const float* __restrict__ mask,
                                              float* __restrict__ out) {
    __shared__ unsigned char sQ[128 * SROW2];
    __shared__ unsigned char sK[128 * SROW2];
    __shared__ float s_rs[128], s_ra[128], s_cm[128], s_ca[128];

    int ntb = blockIdx.x, mtb = blockIdx.y, bh = blockIdx.z;
    int b = bh / HEADS;
    int tid = threadIdx.x, warp = tid >> 5, lane = tid & 31;
    int wm = (warp >> 1) * 32;
    int wn = (warp & 1) * 64;

    const unsigned char* Qb = g_Q + (size_t)bh * SEQ * HEAD_S + (size_t)mtb * 128 * HEAD_S;
    const unsigned char* Kb = g_K + (size_t)bh * SEQ * HEAD_S + (size_t)ntb * 128 * HEAD_S;

    // tile loads: 128 rows x 64 B, 4 threads/row x 16B, 2 iters
    int lrow = tid >> 2, lc = (tid & 3) * 16;
#pragma unroll
    for (int it = 0; it < 2; it++) {
        int row = it * 64 + lrow;
        uint32_t o = row * SROW2 + lc;
        cpasync16s(saddr(sQ) + o, Qb + (size_t)row * HEAD_S + lc);
        cpasync16s(saddr(sK) + o, Kb + (size_t)row * HEAD_S + lc);
    }
    CP_COMMIT;

    if (tid < 128) {
        float m2 = mask[(size_t)b * SEQ + mtb * 128 + tid];
        s_rs[tid] = m2 * (0.125f / (QKSCALE * QKSCALE));
        s_ra[tid] = (1.0f - m2) * (-NEG8);
        float m3 = mask[(size_t)b * SEQ + ntb * 128 + tid];
        s_cm[tid] = m3;
        s_ca[tid] = (1.0f - m3) * (-NEG8);
    }
    CP_WAIT(0);
    __syncthreads();

    float acc[2][8][4];
#pragma unroll
    for (int a = 0; a < 2; a++)
#pragma unroll
        for (int c = 0; c < 8; c++)
#pragma unroll
            for (int d = 0; d < 4; d++) acc[a][c][d] = 0.0f;

    uint32_t qb = saddr(sQ), kb8 = saddr(sK);
#pragma unroll
    for (int ks = 0; ks < 2; ks++) {
        int kb = ks * 32;
        unsigned a[2][4], bf[4][4];
#pragma unroll
        for (int mt = 0; mt < 2; mt++) {
            int r = wm + mt * 16 + (lane & 7) + ((lane >> 3) & 1) * 8;
            int c = kb + (lane >> 4) * 16;
            ldmx4(a[mt], qb + r * SROW2 + c);
        }
#pragma unroll
        for (int np = 0; np < 4; np++) {
            int g = lane >> 3;
            int r = wn + np * 16 + (lane & 7) + (g >> 1) * 8;
            int c = kb + (g & 1) * 16;
            ldmx4(bf[np], kb8 + r * SROW2 + c);
        }
#pragma unroll
        for (int mt = 0; mt < 2; mt++)
#pragma unroll
            for (int np = 0; np < 4; np++) {
                mma8(acc[mt][2 * np],     a[mt], &bf[np][0]);
                mma8(acc[mt][2 * np + 1], a[mt], &bf[np][2]);
            }
    }

    float* ob = out + (size_t)bh * (SEQ * SEQ);
#pragma unroll
    for (int mt = 0; mt < 2; mt++) {
#pragma unroll
        for (int rr = 0; rr < 2; rr++) {
            int rl = wm + mt * 16 + (lane >> 2) + rr * 8;
            int row = mtb * 128 + rl;
            float rs = s_rs[rl], ra = s_ra[rl];
#pragma unroll
            for (int nt = 0; nt < 8; nt++) {
                int cl = wn + nt * 8 + 2 * (lane & 3);
                int col = ntb * 128 + cl;
                float v0 = (acc[mt][nt][rr * 2 + 0] * rs + ra) * s_cm[cl] + s_ca[cl];
                float v1 = (acc[mt][nt][rr * 2 + 1] * rs + ra) * s_cm[cl + 1] + s_ca[cl + 1];
                if (row > col)     v0 -= NEG8;
                if (row > col + 1) v1 -= NEG8;
                __stcs((float2*)&ob[(size_t)row * SEQ + col], make_float2(v0, v1));
            }
        }
    }
}

extern "C" void kernel_launch(void* const* d_in, const int* in_sizes, int n_in,
                              void* d_out, int out_size) {
    const float* x    = (const float*)d_in[0];
    const float* mask = (const float*)d_in[1];
    const float* W    = (const float*)d_in[2];
    const float* bias = (const float*)d_in[3];
    float* out = (float*)d_out;

    cudaFuncSetAttribute(stage1, cudaFuncAttributeMaxDynamicSharedMemorySize, S1_SMEM);

    prep<<<PREP_XBLK + PREP_WBLK + PREP_RBLK, 256>>>(x, W);
    stage1<<<dim3(HEADS, MROWS / 128), 256, S1_SMEM>>>(bias);
    stage2<<<dim3(4, 4, BATCH * HEADS), 256>>>(mask, out);
}

// round 5
// speedup vs baseline: 1.1707x; 1.1707x over previous
#include <cuda_runtime.h>
#include <cuda_bf16.h>
#include <cstdint>

#define HEADS 12
#define HEAD_S 64
#define BATCH 32
#define SEQ 512
#define DIM 768
#define NPROJ (HEADS * HEAD_S * 2)   // 1536
#define MROWS (BATCH * SEQ)          // 16384
#define NEGC 1000000000000.0f
#define NEG8 (NEGC * 0.125f)

// -------- scratch (device globals; no allocation allowed) --------
__device__ __nv_bfloat16 g_x[(size_t)MROWS * DIM];             // bf16 copy of x
__device__ __nv_bfloat16 g_Wt[NPROJ * DIM];                    // [n][k] transposed bf16 W
__device__ __nv_bfloat16 g_Q[(size_t)BATCH * HEADS * SEQ * HEAD_S];
__device__ __nv_bfloat16 g_K[(size_t)BATCH * HEADS * SEQ * HEAD_S];
__device__ float g_sin[SEQ * 32];
__device__ float g_cos[SEQ * 32];

// -------- helpers --------
__device__ __forceinline__ uint32_t saddr(const void* p) {
    return (uint32_t)__cvta_generic_to_shared(p);
}
__device__ __forceinline__ unsigned pk(float a, float b) {
    __nv_bfloat162 h = __floats2bfloat162_rn(a, b);
    return *reinterpret_cast<unsigned*>(&h);
}
__device__ __forceinline__ void cpasync16s(uint32_t s, const void* gmem) {
    asm volatile("cp.async.cg.shared.global [%0], [%1], 16;" :: "r"(s), "l"(gmem));
}
#define CP_COMMIT asm volatile("cp.async.commit_group;")
#define CP_WAIT(n) asm volatile("cp.async.wait_group %0;" :: "n"(n))

__device__ __forceinline__ void ldmx4(unsigned* r, uint32_t addr) {
    asm volatile("ldmatrix.sync.aligned.m8n8.x4.shared.b16 {%0,%1,%2,%3},[%4];"
                 : "=r"(r[0]), "=r"(r[1]), "=r"(r[2]), "=r"(r[3]) : "r"(addr));
}
__device__ __forceinline__ void mma16816(float* c, const unsigned* a, const unsigned* b) {
    asm volatile(
        "mma.sync.aligned.m16n8k16.row.col.f32.bf16.bf16.f32 "
        "{%0,%1,%2,%3},{%4,%5,%6,%7},{%8,%9},{%0,%1,%2,%3};"
        : "+f"(c[0]), "+f"(c[1]), "+f"(c[2]), "+f"(c[3])
        : "r"(a[0]), "r"(a[1]), "r"(a[2]), "r"(a[3]), "r"(b[0]), "r"(b[1]));
}

// =============================================================
// Fused prep: x->bf16 (0..6143), W transpose (6144..7295), rope (7296..7359)
// =============================================================
#define PREP_XBLK 6144
#define PREP_WBLK 1152
#define PREP_RBLK 64
__global__ __launch_bounds__(256) void prep(const float* __restrict__ x,
                                            const float* __restrict__ W) {
    __shared__ float t[32][33];
    int bid = blockIdx.x, tid = threadIdx.x;
    if (bid < PREP_XBLK) {
        size_t i = ((size_t)bid * 256 + tid) * 8;
        const float4* p = (const float4*)(x + i);
        float4 u = p[0], v = p[1];
        uint4 w;
        w.x = pk(u.x, u.y); w.y = pk(u.z, u.w);
        w.z = pk(v.x, v.y); w.w = pk(v.z, v.w);
        *(uint4*)&g_x[i] = w;
    } else if (bid < PREP_XBLK + PREP_WBLK) {
        int tile = bid - PREP_XBLK;
        int nt = (tile % 48) * 32, kt = (tile / 48) * 32;
        int tx = tid & 31, ty = tid >> 5;
        for (int i2 = ty; i2 < 32; i2 += 8)
            t[i2][tx] = W[(size_t)(kt + i2) * NPROJ + nt + tx];
        __syncthreads();
        for (int i2 = ty; i2 < 32; i2 += 8)
            g_Wt[(size_t)(nt + i2) * DIM + kt + tx] = __float2bfloat16(t[tx][i2]);
    } else {
        int idx = (bid - PREP_XBLK - PREP_WBLK) * 256 + tid;  // < 16384
        int l = idx >> 5, i2 = idx & 31;
        float freq = powf(10000.0f, -(2.0f * (float)i2) / 64.0f);
        float ang = (float)l * freq;
        g_sin[idx] = sinf(ang);
        g_cos[idx] = cosf(ang);
    }
}

// =============================================================
// Stage 1: proj = x @ W + b, RoPE, write Q/K bf16
// tile 128x128, BK=64, 3-stage cp.async ring, ONE sync per iter
// dynamic smem: 3 * (128*72 A + 128*72 B) bf16 = 110592 B
// =============================================================
#define ABUF (128 * 72)
#define S1_STAGE (2 * ABUF)                 // bf16 elems per stage
#define S1_SMEM (3 * S1_STAGE * 2)          // bytes = 110592

__global__ __launch_bounds__(256, 2) void stage1(const float* __restrict__ bias) {
    extern __shared__ __nv_bfloat16 sm[];
    __shared__ float sBias[128];

    int tid = threadIdx.x, warp = tid >> 5, lane = tid & 31;
    int head = blockIdx.x, mblk = blockIdx.y;
    int wm = (warp >> 1) * 32;
    int wn = (warp & 1) * 64;

    if (tid < 128) sBias[tid] = bias[head * 128 + tid];

    const __nv_bfloat16* xb = g_x + (size_t)mblk * 128 * DIM;
    const __nv_bfloat16* wb = g_Wt + (size_t)head * 128 * DIM;
    int lrow = tid >> 3, lkk = (tid & 7) * 8;

    auto issue = [&](int buf, int t) {
        __nv_bfloat16* sA = sm + buf * S1_STAGE;
        __nv_bfloat16* sB = sA + ABUF;
        const __nv_bfloat16* xp = xb + t * 64 + lkk;
        const __nv_bfloat16* wp = wb + t * 64 + lkk;
#pragma unroll
        for (int it = 0; it < 4; it++) {
            int row = it * 32 + lrow;
            cpasync16s(saddr(&sA[row * 72 + lkk]), xp + (size_t)row * DIM);
            cpasync16s(saddr(&sB[row * 72 + lkk]), wp + (size_t)row * DIM);
        }
        CP_COMMIT;
    };

    float acc[2][8][4];
#pragma unroll
    for (int a = 0; a < 2; a++)
#pragma unroll
        for (int b = 0; b < 8; b++)
#pragma unroll
            for (int c = 0; c < 4; c++) acc[a][b][c] = 0.0f;

    issue(0, 0); issue(1, 1); issue(2, 2);

    const int NK = DIM / 64;   // 12
    for (int i = 0; i < NK; i++) {
        if (i <= NK - 2) { CP_WAIT(1); } else { CP_WAIT(0); }
        __syncthreads();
        // refill the buffer consumed at iter i-1 (barrier above protects it)
        if (i >= 1 && i + 2 < NK) issue((i - 1) % 3, i + 2);

        const __nv_bfloat16* cA = sm + (i % 3) * S1_STAGE;
        const __nv_bfloat16* cB = cA + ABUF;
#pragma unroll
        for (int ks = 0; ks < 4; ks++) {
            int kb = ks * 16;
            unsigned a[2][4], bf[4][4];
#pragma unroll
            for (int mt = 0; mt < 2; mt++) {
                int r = wm + mt * 16 + (lane & 7) + ((lane >> 3) & 1) * 8;
                int c = kb + (lane >> 4) * 8;
                ldmx4(a[mt], saddr(&cA[r * 72 + c]));
            }
#pragma unroll
            for (int np = 0; np < 4; np++) {
                int g = lane >> 3;
                int r = wn + np * 16 + (lane & 7) + (g >> 1) * 8;
                int c = kb + (g & 1) * 8;
                ldmx4(bf[np], saddr(&cB[r * 72 + c]));
            }
#pragma unroll
            for (int mt = 0; mt < 2; mt++)
#pragma unroll
                for (int np = 0; np < 4; np++) {
                    mma16816(acc[mt][2 * np], a[mt], &bf[np][0]);
                    mma16816(acc[mt][2 * np + 1], a[mt], &bf[np][2]);
                }
        }
    }

    // epilogue: bias + RoPE, write Q/K bf16
    int gmb = mblk * 128;
#pragma unroll
    for (int mt = 0; mt < 2; mt++) {
#pragma unroll
        for (int nt = 0; nt < 8; nt++) {
            int ncol = wn + nt * 8 + 2 * (lane & 3);   // even, [0,128)
            int rch = ncol & 63;
            int i = rch >> 1;
            bool isQ = ncol < 64;
            float b0 = sBias[ncol], b1 = sBias[ncol + 1];
#pragma unroll
            for (int rr = 0; rr < 2; rr++) {
                int row = wm + mt * 16 + (lane >> 2) + rr * 8;
                int gm = gmb + row;
                int bb = gm >> 9;
                int l = gm & 511;
                float v0 = acc[mt][nt][rr * 2 + 0] + b0;
                float v1 = acc[mt][nt][rr * 2 + 1] + b1;
                float sn = g_sin[l * 32 + i], cs = g_cos[l * 32 + i];
                float o0 = v0 * cs - v1 * sn;
                float o1 = v1 * cs + v0 * sn;
                size_t off = (((size_t)(bb * HEADS + head) * SEQ + l) * HEAD_S + rch);
                __nv_bfloat16* dst = (isQ ? g_Q : g_K) + off;
                *(__nv_bfloat162*)dst = __floats2bfloat162_rn(o0, o1);
            }
        }
    }
}

// =============================================================
// Stage 2: per (b,h): full 128x512 strip per CTA.
// Q tile (128x64) + whole K (512x64) in smem, loaded once, one sync.
// grid (4 mtiles, 384 bh)
// =============================================================
#define S2_Q_OFF 0
#define S2_K_OFF (128 * 72 * 2)                       // 18432
#define S2_RS_OFF (S2_K_OFF + 512 * 72 * 2)           // 92160
#define S2_RA_OFF (S2_RS_OFF + 128 * 4)
#define S2_CM_OFF (S2_RA_OFF + 128 * 4)
#define S2_CA_OFF (S2_CM_OFF + 512 * 4)
#define S2_SMEM   (S2_CA_OFF + 512 * 4)               // 97280

__global__ __launch_bounds__(256, 2) void stage2(const float* __restrict__ mask,
                                                 float* __restrict__ out) {
    extern __shared__ char sm2[];
    __nv_bfloat16* sQ = (__nv_bfloat16*)(sm2 + S2_Q_OFF);
    __nv_bfloat16* sK = (__nv_bfloat16*)(sm2 + S2_K_OFF);
    float* s_rs = (float*)(sm2 + S2_RS_OFF);
    float* s_ra = (float*)(sm2 + S2_RA_OFF);
    float* s_cm = (float*)(sm2 + S2_CM_OFF);
    float* s_ca = (float*)(sm2 + S2_CA_OFF);

    int mtb = blockIdx.x, bh = blockIdx.y;
    int b = bh / HEADS;
    int tid = threadIdx.x, warp = tid >> 5, lane = tid & 31;
    int wm = (warp >> 1) * 32;
    int wn = (warp & 1) * 64;

    const __nv_bfloat16* Qb = g_Q + (size_t)bh * SEQ * HEAD_S + (size_t)mtb * 128 * HEAD_S;
    const __nv_bfloat16* Kb = g_K + (size_t)bh * SEQ * HEAD_S;

    int lrow = tid >> 3, lkk = (tid & 7) * 8;
#pragma unroll
    for (int it = 0; it < 4; it++) {
        int row = it * 32 + lrow;
        cpasync16s(saddr(&sQ[row * 72 + lkk]), Qb + (size_t)row * HEAD_S + lkk);
    }
#pragma unroll
    for (int it = 0; it < 16; it++) {
        int row = it * 32 + lrow;
        cpasync16s(saddr(&sK[row * 72 + lkk]), Kb + (size_t)row * HEAD_S + lkk);
    }
    CP_COMMIT;

    // mask precompute overlapped with loads
    const float* mrow = mask + (size_t)b * SEQ;
    if (tid < 128) {
        float m2 = mrow[mtb * 128 + tid];
        s_rs[tid] = m2 * 0.125f;
        s_ra[tid] = (1.0f - m2) * (-NEG8);
    }
#pragma unroll
    for (int q = 0; q < 2; q++) {
        int cidx = q * 256 + tid;
        float m3 = mrow[cidx];
        s_cm[cidx] = m3;
        s_ca[cidx] = (1.0f - m3) * (-NEG8);
    }
    CP_WAIT(0);
    __syncthreads();

    float* ob = out + (size_t)bh * (SEQ * SEQ);

    for (int ntb = 0; ntb < 4; ntb++) {
        float acc[2][8][4];
#pragma unroll
        for (int a = 0; a < 2; a++)
#pragma unroll
            for (int c = 0; c < 8; c++)
#pragma unroll
                for (int d = 0; d < 4; d++) acc[a][c][d] = 0.0f;

#pragma unroll
        for (int ks = 0; ks < 4; ks++) {
            int kb = ks * 16;
            unsigned a[2][4], bf[4][4];
#pragma unroll
            for (int mt = 0; mt < 2; mt++) {
                int r = wm + mt * 16 + (lane & 7) + ((lane >> 3) & 1) * 8;
                int c = kb + (lane >> 4) * 8;
                ldmx4(a[mt], saddr(&sQ[r * 72 + c]));
            }
#pragma unroll
            for (int np = 0; np < 4; np++) {
                int g = lane >> 3;
                int r = ntb * 128 + wn + np * 16 + (lane & 7) + (g >> 1) * 8;
                int c = kb + (g & 1) * 8;
                ldmx4(bf[np], saddr(&sK[r * 72 + c]));
            }
#pragma unroll
            for (int mt = 0; mt < 2; mt++)
#pragma unroll
                for (int np = 0; np < 4; np++) {
                    mma16816(acc[mt][2 * np], a[mt], &bf[np][0]);
                    mma16816(acc[mt][2 * np + 1], a[mt], &bf[np][2]);
                }
        }

        // epilogue: v = (S*rs + ra)*cm + ca - (row>col)*NEG/8 ; streaming stores
#pragma unroll
        for (int mt = 0; mt < 2; mt++) {
#pragma unroll
            for (int rr = 0; rr < 2; rr++) {
                int rl = wm + mt * 16 + (lane >> 2) + rr * 8;
                int row = mtb * 128 + rl;
                float rs = s_rs[rl], ra = s_ra[rl];
#pragma unroll
                for (int nt = 0; nt < 8; nt++) {
                    int col = ntb * 128 + wn + nt * 8 + 2 * (lane & 3);
                    float v0 = (acc[mt][nt][rr * 2 + 0] * rs + ra) * s_cm[col] + s_ca[col];
                    float v1 = (acc[mt][nt][rr * 2 + 1] * rs + ra) * s_cm[col + 1] + s_ca[col + 1];
                    if (row > col)     v0 -= NEG8;
                    if (row > col + 1) v1 -= NEG8;
                    __stcs((float2*)&ob[(size_t)row * SEQ + col], make_float2(v0, v1));
                }
            }
        }
    }
}

extern "C" void kernel_launch(void* const* d_in, const int* in_sizes, int n_in,
                              void* d_out, int out_size) {
    const float* x    = (const float*)d_in[0];
    const float* mask = (const float*)d_in[1];
    const float* W    = (const float*)d_in[2];
    const float* bias = (const float*)d_in[3];
    float* out = (float*)d_out;

    cudaFuncSetAttribute(stage1, cudaFuncAttributeMaxDynamicSharedMemorySize, S1_SMEM);
    cudaFuncSetAttribute(stage2, cudaFuncAttributeMaxDynamicSharedMemorySize, S2_SMEM);

    prep<<<PREP_XBLK + PREP_WBLK + PREP_RBLK, 256>>>(x, W);
    stage1<<<dim3(HEADS, MROWS / 128), 256, S1_SMEM>>>(bias);
    stage2<<<dim3(4, BATCH * HEADS), 256, S2_SMEM>>>(mask, out);
}